// round 6
// baseline (speedup 1.0000x reference)
#include <cuda_runtime.h>
#include <math.h>

// Problem constants
#define B      16384
#define IN     64
#define HID    128
#define E      64
#define NMAP   1000
#define TILE_M 128
#define NBLK   64                      // binning blocks (B/256)
#define MAX_TILES (B / TILE_M + E)     // 192
#define MLP_THREADS 512

// Scratch (device globals; no allocation allowed)
__device__ int g_e[B];
__device__ int g_hist[NBLK * E];       // per-block histogram rows
__device__ int g_expOff[E];
__device__ int g_counts[E];
__device__ int g_bucket[B];
__device__ int g_tileExpert[MAX_TILES];
__device__ int g_tileIdx[MAX_TILES];
__device__ int g_numTiles;

// packed f32x2 FMA (Blackwell; only reachable via PTX)
__device__ __forceinline__ unsigned long long ffma2(unsigned long long a,
                                                    unsigned long long b,
                                                    unsigned long long c) {
    unsigned long long d;
    asm("fma.rn.f32x2 %0, %1, %2, %3;" : "=l"(d) : "l"(a), "l"(b), "l"(c));
    return d;
}

// ---------------------------------------------------------------------------
// K1: expert id per sample + per-block histogram (NO global atomics).
// dtype width of num/c detected per-block (int64 -> odd 32-bit words all zero).
__global__ void hist_kernel(const int* __restrict__ num32,
                            const int* __restrict__ c32) {
    __shared__ int hs[E];
    __shared__ int s_stride;
    int t = threadIdx.x, b = blockIdx.x;
    if (t == 0) {
        int is64 = 1;
        for (int j = 1; j < 64; j += 2)
            if (c32[j] != 0) { is64 = 0; break; }
        s_stride = is64 ? 2 : 1;
    }
    if (t < E) hs[t] = 0;
    __syncthreads();
    int stride = s_stride;
    int i = b * 256 + t;
    int n = num32[(size_t)i * stride];
    n = n < 0 ? 0 : (n >= NMAP ? NMAP - 1 : n);
    int e = c32[(size_t)n * stride];
    e = e < 0 ? 0 : (e >= E ? E - 1 : e);
    g_e[i] = e;
    atomicAdd(&hs[e], 1);
    __syncthreads();
    if (t < E) g_hist[b * E + t] = hs[t];
}

// ---------------------------------------------------------------------------
// K2: scatter with fused scan. Every block recomputes the prefixes it needs
// from g_hist (4KB, L2). Block 0 additionally emits the tile map.
__global__ void scatter_kernel() {
    __shared__ int loc[E];
    __shared__ int basev[E];
    __shared__ int s_wsum[2];    // warp sums for count scan
    __shared__ int s_wsum2[2];   // warp sums for tile scan
    int t = threadIdx.x, b = blockIdx.x;

    int tot = 0, pre = 0, exclC = 0, exclT = 0, nt = 0;
    int lane = t & 31, warp = t >> 5;
    if (t < E) {
        #pragma unroll 4
        for (int bb = 0; bb < NBLK; bb++) {
            int v = g_hist[bb * E + t];
            tot += v;
            if (bb < b) pre += v;
        }
        nt = (tot + TILE_M - 1) / TILE_M;
        // warp-level inclusive scans of (tot, nt)
        int s1 = tot, s2 = nt;
        #pragma unroll
        for (int off = 1; off < 32; off <<= 1) {
            int n1 = __shfl_up_sync(0xFFFFFFFFu, s1, off);
            int n2 = __shfl_up_sync(0xFFFFFFFFu, s2, off);
            if (lane >= off) { s1 += n1; s2 += n2; }
        }
        exclC = s1 - tot;
        exclT = s2 - nt;
        if (lane == 31) { s_wsum[warp] = s1; s_wsum2[warp] = s2; }
    }
    __syncthreads();
    if (t < E) {
        int addC = (warp == 1) ? s_wsum[0]  : 0;
        int addT = (warp == 1) ? s_wsum2[0] : 0;
        int eOff = exclC + addC;
        basev[t] = eOff + pre;
        loc[t]   = 0;
        if (b == 0) {
            g_counts[t] = tot;
            g_expOff[t] = eOff;
            int t0 = exclT + addT;
            for (int j = 0; j < nt; j++) {
                g_tileExpert[t0 + j] = t;
                g_tileIdx[t0 + j]    = j;
            }
            if (t == E - 1) g_numTiles = t0 + nt;
        }
    }
    __syncthreads();
    int i = b * 256 + t;
    int e = g_e[i];
    int r = atomicAdd(&loc[e], 1);
    g_bucket[basev[e] + r] = i;
}

// ---------------------------------------------------------------------------
// K3: per-tile fused MLP. CTA = (expert, 128-sample tile), 512 threads.
// tx = tid&15 -> 8 hidden units; ty = tid>>4 -> 4 samples.
// Packed f32x2 mainloop: X tile stored DUPLICATED ({x,x} pairs) so LDS yields
// broadcast-packed operands directly. SMEM: sW 32KB + sXd 64KB = 96KB.
__global__ __launch_bounds__(MLP_THREADS) void mlp_kernel(
    const float* __restrict__ x,
    const float* __restrict__ W1,
    const float* __restrict__ b1,
    const float* __restrict__ W2,
    const float* __restrict__ b2,
    float* __restrict__ out)
{
    extern __shared__ float smem[];
    float* sW  = smem;                 // [k*128 + h], 8192 floats
    float* sXd = smem + IN * HID;      // [k*256 + 2m(+1)], 16384 floats

    int tile = blockIdx.x;
    if (tile >= g_numTiles) return;

    int e    = g_tileExpert[tile];
    int ti   = g_tileIdx[tile];
    int cnt  = g_counts[e];
    int base = g_expOff[e] + ti * TILE_M;
    int mvalid = cnt - ti * TILE_M;
    if (mvalid > TILE_M) mvalid = TILE_M;

    // ---- Load W1[e]: 2048 float4 across 512 threads (4 each)
    {
        const float4* Wg  = (const float4*)(W1 + (size_t)e * IN * HID);
        float4*       Ws4 = (float4*)sW;
        #pragma unroll
        for (int i = threadIdx.x; i < (IN * HID) / 4; i += MLP_THREADS)
            Ws4[i] = Wg[i];
    }

    // ---- Load X tile transposed + duplicated: 4 threads/row, 16 k each
    {
        int m  = threadIdx.x >> 2;               // 0..127
        int kq = (threadIdx.x & 3) * 16;         // k chunk
        int mc = m < mvalid ? m : (mvalid - 1);  // clamp (outputs guarded)
        int gidx = g_bucket[base + mc];
        const float4* xr = (const float4*)(x + (size_t)gidx * IN + kq);
        #pragma unroll
        for (int q = 0; q < 4; q++) {
            float4 v = xr[q];
            int k0 = kq + q * 4;
            *(float2*)&sXd[(k0 + 0) * 2 * TILE_M + 2 * m] = make_float2(v.x, v.x);
            *(float2*)&sXd[(k0 + 1) * 2 * TILE_M + 2 * m] = make_float2(v.y, v.y);
            *(float2*)&sXd[(k0 + 2) * 2 * TILE_M + 2 * m] = make_float2(v.z, v.z);
            *(float2*)&sXd[(k0 + 3) * 2 * TILE_M + 2 * m] = make_float2(v.w, v.w);
        }
    }
    __syncthreads();

    int tx = threadIdx.x & 15;   // hid group (8 units = 4 packed pairs)
    int ty = threadIdx.x >> 4;   // sample group (4 samples)

    unsigned long long acc[4][4];
    #pragma unroll
    for (int mm = 0; mm < 4; mm++)
        #pragma unroll
        for (int jp = 0; jp < 4; jp++)
            acc[mm][jp] = 0ULL;

    // ---- Mainloop: K=64; per k: 4 LDS.128 + 16 FFMA2 (32 FMA lanes packed)
    #pragma unroll 8
    for (int k = 0; k < IN; k++) {
        ulonglong2 xa = *(const ulonglong2*)&sXd[k * 2 * TILE_M + ty * 8];
        ulonglong2 xb = *(const ulonglong2*)&sXd[k * 2 * TILE_M + ty * 8 + 4];
        ulonglong2 w0 = *(const ulonglong2*)&sW[k * HID + tx * 8];
        ulonglong2 w1 = *(const ulonglong2*)&sW[k * HID + tx * 8 + 4];
        unsigned long long am[4] = {xa.x, xa.y, xb.x, xb.y};
        unsigned long long wp[4] = {w0.x, w0.y, w1.x, w1.y};
        #pragma unroll
        for (int mm = 0; mm < 4; mm++)
            #pragma unroll
            for (int jp = 0; jp < 4; jp++)
                acc[mm][jp] = ffma2(am[mm], wp[jp], acc[mm][jp]);
    }

    // ---- Epilogue: +b1, relu, partial dot with w2, reduce over 16 tx groups
    float b1r[8], w2r[8];
    {
        const float* b1e = b1 + (size_t)e * HID + tx * 8;
        const float* w2e = W2 + (size_t)e * HID + tx * 8;   // OUT=1
        #pragma unroll
        for (int j = 0; j < 8; j++) { b1r[j] = b1e[j]; w2r[j] = w2e[j]; }
    }

    __syncthreads();   // done reading sW/sXd; reuse sXd as reduction buffer

    #pragma unroll
    for (int mm = 0; mm < 4; mm++) {
        float p = 0.0f;
        #pragma unroll
        for (int jp = 0; jp < 4; jp++) {
            float2 f = *(float2*)&acc[mm][jp];
            float h0 = f.x + b1r[2 * jp];
            float h1 = f.y + b1r[2 * jp + 1];
            h0 = h0 > 0.0f ? h0 : 0.0f;
            h1 = h1 > 0.0f ? h1 : 0.0f;
            p = fmaf(h0, w2r[2 * jp], p);
            p = fmaf(h1, w2r[2 * jp + 1], p);
        }
        sXd[(ty * 4 + mm) * 17 + tx] = p;
    }
    __syncthreads();

    if (threadIdx.x < TILE_M) {
        int m = threadIdx.x;
        if (m < mvalid) {
            float s = 0.0f;
            #pragma unroll
            for (int t = 0; t < 16; t++) s += sXd[m * 17 + t];
            float y = s + b2[e];
            int gidx = g_bucket[base + m];
            out[gidx] = 1.0f / (1.0f + expf(-y));
        }
    }
}

// ---------------------------------------------------------------------------
extern "C" void kernel_launch(void* const* d_in, const int* in_sizes, int n_in,
                              void* d_out, int out_size) {
    const float* x     = (const float*)d_in[0];
    const int*   num32 = (const int*)d_in[1];
    const int*   c32   = (const int*)d_in[2];
    const float* W1    = (const float*)d_in[3];
    const float* b1    = (const float*)d_in[4];
    const float* W2    = (const float*)d_in[5];
    const float* b2    = (const float*)d_in[6];
    float*       out   = (float*)d_out;

    static bool attr_set = false;
    if (!attr_set) {
        cudaFuncSetAttribute(mlp_kernel,
                             cudaFuncAttributeMaxDynamicSharedMemorySize,
                             96 * 1024);
        attr_set = true;
    }

    hist_kernel<<<NBLK, 256>>>(num32, c32);
    scatter_kernel<<<NBLK, 256>>>();
    mlp_kernel<<<MAX_TILES, MLP_THREADS, 96 * 1024>>>(x, W1, b1, W2, b2, out);
}

// round 8
// speedup vs baseline: 1.4806x; 1.4806x over previous
#include <cuda_runtime.h>
#include <math.h>

// Problem constants
#define B      16384
#define IN     64
#define HID    128
#define E      64
#define NMAP   1000
#define TILE_M 64
#define NBLK   64                       // binning blocks (B/256)
#define MAX_TILES (B / TILE_M + E)      // 320
#define MLP_THREADS 128

// Scratch (device globals; no allocation allowed)
__device__ int g_e[B];
__device__ int g_hist[NBLK * E];        // per-block histogram rows
__device__ int g_expOff[E];
__device__ int g_counts[E];
__device__ int g_bucket[B];
__device__ int g_tileExpert[MAX_TILES];
__device__ int g_tileIdx[MAX_TILES];
__device__ int g_numTiles;
__device__ int g_bar1;                  // inter-phase arrive counter
__device__ int g_bar2;                  // completion counter (for reset)

// ---------------------------------------------------------------------------
// K1: fused binning. grid=64 (all resident) x 256 threads.
// Phase A: expert ids + per-block histogram. Device-wide barrier.
// Phase B: per-block prefix scan from g_hist + counting-sort scatter;
//          block 0 also emits the tile map. Barrier counters self-reset.
__global__ __launch_bounds__(256) void bin_kernel(const int* __restrict__ num32,
                                                  const int* __restrict__ c32) {
    __shared__ int hs[E];
    __shared__ int s_stride;
    __shared__ int basev[E];
    __shared__ int s_wsum[2], s_wsum2[2];
    int t = threadIdx.x, b = blockIdx.x;
    int lane = t & 31, warp = t >> 5;

    // ---- Phase A: histogram
    if (t == 0) {
        int is64 = 1;
        for (int j = 1; j < 64; j += 2)
            if (c32[j] != 0) { is64 = 0; break; }
        s_stride = is64 ? 2 : 1;
    }
    if (t < E) hs[t] = 0;
    __syncthreads();
    int stride = s_stride;
    int i = b * 256 + t;
    int n = num32[(size_t)i * stride];
    n = n < 0 ? 0 : (n >= NMAP ? NMAP - 1 : n);
    int e = c32[(size_t)n * stride];
    e = e < 0 ? 0 : (e >= E ? E - 1 : e);
    g_e[i] = e;
    atomicAdd(&hs[e], 1);
    __syncthreads();
    if (t < E) g_hist[b * E + t] = hs[t];
    __threadfence();

    // ---- Device-wide barrier (all 64 CTAs resident; deterministic reset below)
    if (t == 0) {
        atomicAdd(&g_bar1, 1);
        while (atomicAdd(&g_bar1, 0) < NBLK) { }
    }
    __syncthreads();

    // ---- Phase B: scans + scatter
    int tot = 0, pre = 0, exclC = 0, exclT = 0, nt = 0;
    if (t < E) {
        hs[t] = 0;   // reuse as local rank counter
        #pragma unroll 4
        for (int bb = 0; bb < NBLK; bb++) {
            int v = g_hist[bb * E + t];
            tot += v;
            if (bb < b) pre += v;
        }
        nt = (tot + TILE_M - 1) / TILE_M;
        int s1 = tot, s2 = nt;
        #pragma unroll
        for (int off = 1; off < 32; off <<= 1) {
            int n1 = __shfl_up_sync(0xFFFFFFFFu, s1, off);
            int n2 = __shfl_up_sync(0xFFFFFFFFu, s2, off);
            if (lane >= off) { s1 += n1; s2 += n2; }
        }
        exclC = s1 - tot;
        exclT = s2 - nt;
        if (lane == 31) { s_wsum[warp] = s1; s_wsum2[warp] = s2; }
    }
    __syncthreads();
    if (t < E) {
        int addC = (warp == 1) ? s_wsum[0]  : 0;
        int addT = (warp == 1) ? s_wsum2[0] : 0;
        int eOff = exclC + addC;
        basev[t] = eOff + pre;
        if (b == 0) {
            g_counts[t] = tot;
            g_expOff[t] = eOff;
            int t0 = exclT + addT;
            for (int j = 0; j < nt; j++) {
                g_tileExpert[t0 + j] = t;
                g_tileIdx[t0 + j]    = j;
            }
            if (t == E - 1) g_numTiles = t0 + nt;
        }
    }
    __syncthreads();
    int r = atomicAdd(&hs[e], 1);
    g_bucket[basev[e] + r] = i;

    // ---- Completion + deterministic counter reset for graph replay
    __syncthreads();
    if (t == 0) {
        int d = atomicAdd(&g_bar2, 1);
        if (d == NBLK - 1) { g_bar1 = 0; g_bar2 = 0; }
    }
}

// ---------------------------------------------------------------------------
// K2: per-tile fused MLP. CTA = (expert, 64-sample tile), 128 threads.
// tx = tid&15 -> 8 hidden units; ty = tid>>4 -> 8 samples. 8x8 register tile.
// Static SMEM 48KB -> ~4 CTAs/SM resident; grid up to 320 fits one wave.
__global__ __launch_bounds__(MLP_THREADS) void mlp_kernel(
    const float* __restrict__ x,
    const float* __restrict__ W1,
    const float* __restrict__ b1,
    const float* __restrict__ W2,
    const float* __restrict__ b2,
    float* __restrict__ out)
{
    __shared__ float sW[IN * HID];      // [k*128 + h]  32KB
    __shared__ float sX[IN * TILE_M];   // [k*64 + m]   16KB

    int tile = blockIdx.x;
    if (tile >= g_numTiles) return;

    int e    = g_tileExpert[tile];
    int ti   = g_tileIdx[tile];
    int cnt  = g_counts[e];
    int base = g_expOff[e] + ti * TILE_M;
    int mvalid = cnt - ti * TILE_M;
    if (mvalid > TILE_M) mvalid = TILE_M;

    // ---- Load W1[e]: 2048 float4 across 128 threads (16 each)
    {
        const float4* Wg  = (const float4*)(W1 + (size_t)e * IN * HID);
        float4*       Ws4 = (float4*)sW;
        #pragma unroll
        for (int i = threadIdx.x; i < (IN * HID) / 4; i += MLP_THREADS)
            Ws4[i] = Wg[i];
    }

    // ---- Load X tile transposed: 2 threads/row, 32-float half-rows
    {
        int m  = threadIdx.x >> 1;               // 0..63
        int kq = (threadIdx.x & 1) * 32;
        int mc = m < mvalid ? m : (mvalid - 1);  // clamp (outputs guarded)
        int gidx = g_bucket[base + mc];
        const float4* xr = (const float4*)(x + (size_t)gidx * IN + kq);
        #pragma unroll
        for (int q = 0; q < 8; q++) {
            float4 v = xr[q];
            int k0 = kq + q * 4;
            sX[(k0 + 0) * TILE_M + m] = v.x;
            sX[(k0 + 1) * TILE_M + m] = v.y;
            sX[(k0 + 2) * TILE_M + m] = v.z;
            sX[(k0 + 3) * TILE_M + m] = v.w;
        }
    }
    __syncthreads();

    int tx = threadIdx.x & 15;   // hid group (8 units)
    int ty = threadIdx.x >> 4;   // sample group (8 samples)

    float acc[8][8];
    #pragma unroll
    for (int mm = 0; mm < 8; mm++)
        #pragma unroll
        for (int j = 0; j < 8; j++)
            acc[mm][j] = 0.0f;

    // ---- Mainloop: K=64, 8x8 register tile (64 FMA per k per thread)
    #pragma unroll 4
    for (int k = 0; k < IN; k++) {
        float4 a0 = *(const float4*)&sX[k * TILE_M + ty * 8];
        float4 a1 = *(const float4*)&sX[k * TILE_M + ty * 8 + 4];
        float4 w0 = *(const float4*)&sW[k * HID + tx * 8];
        float4 w1 = *(const float4*)&sW[k * HID + tx * 8 + 4];
        float a[8]  = {a0.x, a0.y, a0.z, a0.w, a1.x, a1.y, a1.z, a1.w};
        float bb[8] = {w0.x, w0.y, w0.z, w0.w, w1.x, w1.y, w1.z, w1.w};
        #pragma unroll
        for (int mm = 0; mm < 8; mm++)
            #pragma unroll
            for (int j = 0; j < 8; j++)
                acc[mm][j] = fmaf(a[mm], bb[j], acc[mm][j]);
    }

    // ---- Epilogue: +b1, relu, partial dot with w2, reduce over 16 tx groups
    float b1r[8], w2r[8];
    {
        const float* b1e = b1 + (size_t)e * HID + tx * 8;
        const float* w2e = W2 + (size_t)e * HID + tx * 8;   // OUT=1
        #pragma unroll
        for (int j = 0; j < 8; j++) { b1r[j] = b1e[j]; w2r[j] = w2e[j]; }
    }

    __syncthreads();   // done reading sX/sW; reuse sX as reduction buffer
    // reduction buffer: sX[row*17 + tx], rows 0..63 (padded stride 17)

    #pragma unroll
    for (int mm = 0; mm < 8; mm++) {
        float p = 0.0f;
        #pragma unroll
        for (int j = 0; j < 8; j++) {
            float h = acc[mm][j] + b1r[j];
            h = h > 0.0f ? h : 0.0f;
            p = fmaf(h, w2r[j], p);
        }
        sX[(ty * 8 + mm) * 17 + tx] = p;
    }
    __syncthreads();

    if (threadIdx.x < TILE_M) {
        int m = threadIdx.x;
        if (m < mvalid) {
            float s = 0.0f;
            #pragma unroll
            for (int t = 0; t < 16; t++) s += sX[m * 17 + t];
            float y = s + b2[e];
            int gidx = g_bucket[base + m];
            out[gidx] = 1.0f / (1.0f + expf(-y));
        }
    }
}

// ---------------------------------------------------------------------------
extern "C" void kernel_launch(void* const* d_in, const int* in_sizes, int n_in,
                              void* d_out, int out_size) {
    const float* x     = (const float*)d_in[0];
    const int*   num32 = (const int*)d_in[1];
    const int*   c32   = (const int*)d_in[2];
    const float* W1    = (const float*)d_in[3];
    const float* b1    = (const float*)d_in[4];
    const float* W2    = (const float*)d_in[5];
    const float* b2    = (const float*)d_in[6];
    float*       out   = (float*)d_out;

    static bool attr_set = false;
    if (!attr_set) {
        cudaFuncSetAttribute(mlp_kernel,
                             cudaFuncAttributePreferredSharedMemoryCarveout, 100);
        attr_set = true;
    }

    bin_kernel<<<NBLK, 256>>>(num32, c32);
    mlp_kernel<<<MAX_TILES, MLP_THREADS>>>(x, W1, b1, W2, b2, out);
}